// round 14
// baseline (speedup 1.0000x reference)
#include <cuda_runtime.h>
#include <cstdint>
#include <math.h>

#define Bq    8
#define Sq    512
#define Dm    768
#define Hh    12
#define Dk    64
#define BHn   (Bq*Hh)            // 96
#define Mrows (Bq*Sq)            // 4096
#define NATT  (25165824)         // B*H*S*S
#define SCALE 0.036084391824351615f   // 1/sqrt(768)
#define PW    384                // packed words per row (Dm/2)
#define PSTR  ((size_t)Mrows*PW) // words per projection plane (== Hh*Mrows*32)

// ---- projection GEMM tiling (bf16 m16n8k16, 3x split) ----
#define BM 128
#define BN 64
#define APL 2560                 // A plane words per stage: 128*20
#define BPL 1280                 // B plane words per stage: 64*20
#define STAGE_W (2*APL + 2*BPL)  // 7680 words
#define DYN_SMEM (2*STAGE_W*4)   // 61440 bytes
#define NSTAGE (Dm/32)           // 24

// ---- attn smem layout (4B words), 32 q-rows per block, swizzled stride-32 ----
#define QROWS 32
#define KBUFW 8192               // K chunk buffer: 2 planes x 128 tok x 32 words
#define SS_STR 520
#define OFF_SQ   0                               // 2 planes x 32 x 32 = 2048
#define OFF_SKB  2048                            // 2 bufs x 8192 = 16384
#define OFF_SS   18432                           // 32 x 520 = 16640
#define OFF_SMK  35072                           // 32 x 512 = 16384
#define OFF_RED  51456                           // 32
#define OFF_W    51488                           // 8
#define ATTN_SMEM_BYTES  ((OFF_W + 8)*4)         // 205984

// Scratch (device globals: allocation-free, graph-capturable)
__device__ uint32_t g_qkP[(size_t)2 * 2 * Mrows * PW];   // [mat][plane] query,key packed
__device__ uint32_t g_wP[(size_t)6 * 2 * Dm * PW];       // [w][plane] W^T packed
// projections, head-major + 16B-group swizzle: [w*2+plane][h][row][32 words]
__device__ uint32_t g_projP[(size_t)12 * PSTR];
__device__ double g_loss;

struct Ptr6 { const float* p[6]; };

// ---------------------------------------------------------------------------
// helpers
// ---------------------------------------------------------------------------
__device__ __forceinline__ uint32_t smem_u32(const void* p) {
    uint32_t a;
    asm("{ .reg .u64 t; cvta.to.shared.u64 t, %1; cvt.u32.u64 %0, t; }"
        : "=r"(a) : "l"(p));
    return a;
}
__device__ __forceinline__ void cp16(uint32_t s, const void* g) {
    asm volatile("cp.async.ca.shared.global [%0], [%1], 16;"
                 :: "r"(s), "l"(g) : "memory");
}
__device__ __forceinline__ void cp_commit() {
    asm volatile("cp.async.commit_group;" ::: "memory");
}
template <int N>
__device__ __forceinline__ void cp_wait() {
    asm volatile("cp.async.wait_group %0;" :: "n"(N) : "memory");
}
__device__ __forceinline__ void bulk_cp(uint32_t smem, const void* g, uint32_t bytes,
                                        uint32_t mbar) {
    asm volatile(
        "cp.async.bulk.shared::cta.global.mbarrier::complete_tx::bytes [%0], [%1], %2, [%3];"
        :: "r"(smem), "l"(g), "r"(bytes), "r"(mbar) : "memory");
}
__device__ __forceinline__ void mbar_expect(uint32_t mbar, uint32_t bytes) {
    asm volatile("mbarrier.arrive.expect_tx.shared.b64 _, [%0], %1;"
                 :: "r"(mbar), "r"(bytes) : "memory");
}
__device__ __forceinline__ void mbar_wait(uint32_t mbar, uint32_t parity) {
    asm volatile(
        "{\n\t.reg .pred P;\n"
        "WL_%=:\n\t"
        "mbarrier.try_wait.parity.acquire.cta.shared::cta.b64 P, [%0], %1, 0x989680;\n\t"
        "@P bra WD_%=;\n\t"
        "bra WL_%=;\n"
        "WD_%=:\n\t}"
        :: "r"(mbar), "r"(parity) : "memory");
}
// ldmatrix x4: one instr loads 4 fragment registers
__device__ __forceinline__ void ldsm4(uint32_t* r, uint32_t addr) {
    asm volatile("ldmatrix.sync.aligned.m8n8.x4.shared.b16 {%0,%1,%2,%3}, [%4];"
        : "=r"(r[0]), "=r"(r[1]), "=r"(r[2]), "=r"(r[3]) : "r"(addr));
}
// bf16 hi/lo split (bit ops only; Sterbenz => a-hi exact)
__device__ __forceinline__ void splitb(float a, uint32_t& hb, uint32_t& lb) {
    uint32_t u = __float_as_uint(a);
    hb = u & 0xFFFF0000u;
    float l = a - __uint_as_float(hb);
    lb = __float_as_uint(l) & 0xFFFF0000u;
}
__device__ __forceinline__ uint32_t packw(uint32_t b0, uint32_t b1) {
    return b1 | (b0 >> 16);
}
__device__ __forceinline__ void mma16(float* c, const uint32_t* a, const uint32_t* b) {
    asm volatile(
        "mma.sync.aligned.m16n8k16.row.col.f32.bf16.bf16.f32 "
        "{%0,%1,%2,%3}, {%4,%5,%6,%7}, {%8,%9}, {%0,%1,%2,%3};"
        : "+f"(c[0]), "+f"(c[1]), "+f"(c[2]), "+f"(c[3])
        : "r"(a[0]), "r"(a[1]), "r"(a[2]), "r"(a[3]), "r"(b[0]), "r"(b[1]));
}
// word swizzle within a 32-word row: 16B group index XOR (row & 7)
__device__ __forceinline__ int swz(int word, int row) {
    return (word & 3) | ((((word >> 2) ^ row) & 7) << 2);
}
// ln(1+e^-p) for p in [0,1], no MUFU (Taylor, err ~1.5e-8)
__device__ __forceinline__ float softplus_neg01(float p) {
    float x = 0.5f * p;
    float y = x * x;
    float lc = y * (0.5f + y * (-8.3333333333e-2f + y * (2.2222222222e-2f +
               y * (-6.7460317460e-3f + y * (2.1869488536e-3f +
               y * (-7.3860295563e-4f))))));
    return 0.69314718056f - x + lc;
}

// ---------------------------------------------------------------------------
// Pack query/key into bf16 hi/lo planes (also zeroes g_loss).
// ---------------------------------------------------------------------------
__global__ void pack_qk(const float* __restrict__ query, const float* __restrict__ key) {
    if (blockIdx.x == 0 && blockIdx.y == 0 && threadIdx.x == 0) g_loss = 0.0;
    int mat = blockIdx.y;
    const float* src = mat ? key : query;
    uint32_t* hi = g_qkP + (size_t)(mat * 2 + 0) * Mrows * PW;
    uint32_t* lo = g_qkP + (size_t)(mat * 2 + 1) * Mrows * PW;
    int idx = blockIdx.x * 256 + threadIdx.x;
    float2 v = *(const float2*)&src[(size_t)idx * 2];
    uint32_t h0, l0, h1, l1;
    splitb(v.x, h0, l0);
    splitb(v.y, h1, l1);
    hi[idx] = packw(h0, h1);
    lo[idx] = packw(l0, l1);
}

// ---------------------------------------------------------------------------
// Transpose + pack all 6 weight matrices as bf16 hi/lo planes (n-major).
// ---------------------------------------------------------------------------
__global__ void transpose_pack6(Ptr6 ws) {
    __shared__ float t[32][33];
    int w = blockIdx.z;
    const float* W = ws.p[w];
    uint32_t* Thi = g_wP + (size_t)(w * 2 + 0) * Dm * PW;
    uint32_t* Tlo = g_wP + (size_t)(w * 2 + 1) * Dm * PW;
    int n0 = blockIdx.x * 32, k0 = blockIdx.y * 32;
    int tid = threadIdx.y * 32 + threadIdx.x;
#pragma unroll
    for (int i = 0; i < 4; i++)
        t[threadIdx.y + i * 8][threadIdx.x] =
            W[(size_t)(k0 + threadIdx.y + i * 8) * Dm + n0 + threadIdx.x];
    __syncthreads();
#pragma unroll
    for (int i = 0; i < 2; i++) {
        int lin = i * 256 + tid;
        int n = lin >> 4, j = lin & 15;
        uint32_t h0, l0, h1, l1;
        splitb(t[2 * j][n],     h0, l0);
        splitb(t[2 * j + 1][n], h1, l1);
        size_t idx = (size_t)(n0 + n) * PW + k0 / 2 + j;
        Thi[idx] = packw(h0, h1);
        Tlo[idx] = packw(l0, l1);
    }
}

// ---------------------------------------------------------------------------
// bf16 m16n8k16 GEMM (3x split), ldmatrix fragment loads.
// Epilogue writes projections head-major with baked 16B-group swizzle.
// ---------------------------------------------------------------------------
__global__ __launch_bounds__(256, 2) void gemm_mma(Ptr6 biases)
{
    extern __shared__ uint32_t dsw[];
    const int tid = threadIdx.x, warp = tid >> 5, lane = tid & 31;
    const int g = lane >> 2, t = lane & 3;
    const int wm = (warp >> 1) * 32, wn = (warp & 1) * 32;
    const int a_r = ((lane >> 3) & 1) * 8 + (lane & 7);
    const int a_w = (lane >> 4) * 4;
    const int b_r = (lane >> 4) * 8 + (lane & 7);
    const int b_w = ((lane >> 3) & 1) * 4;

    const int w = blockIdx.z;
    const int mat = w & 1;
    const uint32_t* Asrc = g_qkP + (size_t)(mat * 2) * Mrows * PW;
    const uint32_t* Bsrc = g_wP + (size_t)(w * 2) * Dm * PW;
    uint32_t* Phi = g_projP + (size_t)(w * 2 + 0) * PSTR;
    uint32_t* Plo = g_projP + (size_t)(w * 2 + 1) * PSTR;
    const float* bias = biases.p[w];
    const float scale = mat ? 1.0f : SCALE;
    const int m0 = blockIdx.x * BM, n0 = blockIdx.y * BN;

    const uint32_t sb = smem_u32(dsw);

    auto load_stage = [&](int s, int buf) {
        const int kw = s * 16;
        const uint32_t base = sb + (uint32_t)buf * STAGE_W * 4;
#pragma unroll
        for (int i = 0; i < 4; i++) {
            int id = i * 256 + tid;
            int plane = id >> 9, rem = id & 511;
            int row = rem >> 2, q = rem & 3;
            cp16(base + (uint32_t)(plane * APL + row * 20 + q * 4) * 4,
                 &Asrc[(size_t)plane * Mrows * PW + (size_t)(m0 + row) * PW + kw + q * 4]);
        }
#pragma unroll
        for (int i = 0; i < 2; i++) {
            int id = i * 256 + tid;
            int plane = id >> 8, rem = id & 255;
            int row = rem >> 2, q = rem & 3;
            cp16(base + (uint32_t)(2 * APL + plane * BPL + row * 20 + q * 4) * 4,
                 &Bsrc[(size_t)plane * Dm * PW + (size_t)(n0 + row) * PW + kw + q * 4]);
        }
        cp_commit();
    };

    float acc[2][4][4];
#pragma unroll
    for (int mf = 0; mf < 2; mf++)
#pragma unroll
        for (int nf = 0; nf < 4; nf++)
#pragma unroll
            for (int i = 0; i < 4; i++) acc[mf][nf][i] = 0.0f;

    load_stage(0, 0);

    for (int s = 0; s < NSTAGE; s++) {
        if (s + 1 < NSTAGE) { load_stage(s + 1, (s + 1) & 1); cp_wait<1>(); }
        else                { cp_wait<0>(); }
        __syncthreads();

        const uint32_t st_b = sb + (uint32_t)(s & 1) * STAGE_W * 4;

#pragma unroll
        for (int ks = 0; ks < 2; ks++) {
            const int kw = ks * 8;
            uint32_t ah[2][4], al[2][4], bfr[2][4], blr[2][4];
#pragma unroll
            for (int mf = 0; mf < 2; mf++) {
                uint32_t aaddr = st_b +
                    (uint32_t)((wm + mf * 16 + a_r) * 20 + kw + a_w) * 4;
                ldsm4(ah[mf], aaddr);
                ldsm4(al[mf], aaddr + APL * 4);
            }
#pragma unroll
            for (int np = 0; np < 2; np++) {
                uint32_t baddr = st_b + (uint32_t)(2 * APL) * 4 +
                    (uint32_t)((wn + np * 16 + b_r) * 20 + kw + b_w) * 4;
                ldsm4(bfr[np], baddr);
                ldsm4(blr[np], baddr + BPL * 4);
            }
#pragma unroll
            for (int mf = 0; mf < 2; mf++)
#pragma unroll
                for (int nf = 0; nf < 4; nf++) {
                    const uint32_t* bh = &bfr[nf >> 1][(nf & 1) * 2];
                    const uint32_t* bl = &blr[nf >> 1][(nf & 1) * 2];
                    mma16(acc[mf][nf], ah[mf], bh);
                    mma16(acc[mf][nf], ah[mf], bl);
                    mma16(acc[mf][nf], al[mf], bh);
                }
        }
        __syncthreads();
    }

#pragma unroll
    for (int mf = 0; mf < 2; mf++) {
        int row0 = m0 + wm + mf * 16 + g;
#pragma unroll
        for (int nf = 0; nf < 4; nf++) {
            int col = n0 + wn + nf * 8 + 2 * t;
            int wcol = (n0 + wn + nf * 8) / 2 + t;
            int hh = wcol >> 5, word = wcol & 31;
            float2 bv = *(const float2*)&bias[col];
            float v00 = (acc[mf][nf][0] + bv.x) * scale;
            float v01 = (acc[mf][nf][1] + bv.y) * scale;
            float v10 = (acc[mf][nf][2] + bv.x) * scale;
            float v11 = (acc[mf][nf][3] + bv.y) * scale;
            uint32_t h0, l0, h1, l1;
            size_t idx0 = ((size_t)(hh * Mrows + row0)) * 32 + swz(word, row0);
            size_t idx1 = ((size_t)(hh * Mrows + row0 + 8)) * 32 + swz(word, row0 + 8);
            splitb(v00, h0, l0); splitb(v01, h1, l1);
            Phi[idx0] = packw(h0, h1);
            Plo[idx0] = packw(l0, l1);
            splitb(v10, h0, l0); splitb(v11, h1, l1);
            Phi[idx1] = packw(h0, h1);
            Plo[idx1] = packw(l0, l1);
        }
    }
}

// ---------------------------------------------------------------------------
// Fused attention: 32 q-rows per block, bulk-copy K staging (2 instr/chunk),
// swizzled stride-32 smem, chunk skipping, smk in smem, two-pass consumer.
// ---------------------------------------------------------------------------
__global__ __launch_bounds__(256) void attn_fused(
    const float* __restrict__ mask,
    const float* __restrict__ span, float* __restrict__ out)
{
    extern __shared__ uint32_t smw[];
    uint32_t* sQ  = smw + OFF_SQ;
    uint32_t* sKB = smw + OFF_SKB;
    float* sS  = (float*)(smw + OFF_SS);
    float* sMK = (float*)(smw + OFF_SMK);
    float* sRed= (float*)(smw + OFF_RED);
    float* sW  = (float*)(smw + OFF_W);
    __shared__ __align__(8) unsigned long long s_mbar[2];

    int tid  = threadIdx.x;
    int lane = tid & 31;
    int warp = tid >> 5;        // 0..7
    int g    = lane >> 2, t = lane & 3;
    int rt   = warp >> 2;       // producer row tile (0/1)
    int ct   = warp & 3;        // producer 32-col tile within 128-token chunk
    int half = (tid >> 5) & 1;
    int qg   = tid >> 6;
    int kg   = tid & 63;
    const int a_r = ((lane >> 3) & 1) * 8 + (lane & 7);
    const int a_w = (lane >> 4) * 4;
    const int b_r = (lane >> 4) * 8 + (lane & 7);
    const int b_w = ((lane >> 3) & 1) * 4;

    int bh = blockIdx.y;
    int b = bh / Hh, h = bh % Hh;
    int q0 = blockIdx.x * QROWS;

    const int c_lo = half * 256, c_hi = c_lo + 255;

    float rmk[8], rmq[2][4];
#pragma unroll
    for (int c = 0; c < 8; c++) {
        float mv = mask[b * Sq + kg * 8 + c];
        rmk[c] = (mv == -10000.0f) ? 1.0e9f : mv;
    }
#pragma unroll
    for (int p = 0; p < 2; p++)
#pragma unroll
        for (int r = 0; r < 4; r++) {
            float mv = mask[b * Sq + q0 + p * 16 + qg * 4 + r];
            rmq[p][r] = (mv == -10000.0f) ? 1.0e9f : mv;
        }

    const uint32_t sq_b  = smem_u32(sQ);
    const uint32_t skb_b = smem_u32(sKB);
    const uint32_t mb0 = smem_u32(&s_mbar[0]);
    const uint32_t mb1 = smem_u32(&s_mbar[1]);

    if (tid == 0) {
        asm volatile("mbarrier.init.shared.b64 [%0], 1;" :: "r"(mb0) : "memory");
        asm volatile("mbarrier.init.shared.b64 [%0], 1;" :: "r"(mb1) : "memory");
    }
    __syncthreads();
    uint32_t ph[2] = {0, 0};

    for (int mode = 0; mode < 3; mode++) {
        const uint32_t* Qp = g_projP + (size_t)(mode * 4)     * PSTR;
        const uint32_t* Kp = g_projP + (size_t)(mode * 4 + 2) * PSTR;

        int tc_lo, tc_hi;
        if (mode == 0)      { tc_lo = 0;         tc_hi = (q0 + 31) / 128 + 1; }
        else if (mode == 1) { tc_lo = q0 >> 7;   tc_hi = 4; }
        else                { tc_lo = 0;         tc_hi = 4; }

        auto stageK = [&](int tc, int buf) {
            if (tid == 0) {
                uint32_t mb = buf ? mb1 : mb0;
                mbar_expect(mb, 32768u);
                uint32_t kb = skb_b + (uint32_t)(buf * KBUFW) * 4;
                const uint32_t* s0 = Kp + ((size_t)h * Mrows + b * Sq + tc * 128) * 32;
                bulk_cp(kb,             s0,        16384u, mb);
                bulk_cp(kb + 16384u,    s0 + PSTR, 16384u, mb);
            }
        };

        __syncthreads();   // protect sQ/sS reuse from previous mode
        {   // stage Q: 2 planes x 32 rows x 32 words (already swizzled in global)
#pragma unroll
            for (int i = 0; i < 2; i++) {
                int id = i * 256 + tid;
                int plane = id >> 8, rem = id & 255;
                int row = rem >> 3, gg = (rem & 7) * 4;
                cp16(sq_b + (uint32_t)(plane * 1024 + row * 32 + gg) * 4,
                     &Qp[(size_t)plane * PSTR +
                         ((size_t)h * Mrows + b * Sq + q0 + row) * 32 + gg]);
            }
            cp_commit();
        }
        stageK(tc_lo, 0);

        for (int tc = tc_lo; tc < tc_hi; tc++) {
            const int bufc = (tc - tc_lo) & 1;
            if (tc + 1 < tc_hi) stageK(tc + 1, bufc ^ 1);
            if (tc == tc_lo) cp_wait<0>();               // Q ready (per-thread)
            mbar_wait(bufc ? mb1 : mb0, ph[bufc]);
            ph[bufc] ^= 1;
            __syncthreads();

            const int cb = tc * 128;
            const bool warp_do =
                (mode == 0) ? (cb + ct * 32 <= q0 + 31) :
                (mode == 1) ? (cb + ct * 32 + 31 >= q0) : true;
            if (warp_do) {
                float accp[4][4];
#pragma unroll
                for (int nf = 0; nf < 4; nf++)
#pragma unroll
                    for (int i = 0; i < 4; i++) accp[nf][i] = 0.0f;
                const uint32_t kbb = skb_b + (uint32_t)(bufc * KBUFW) * 4;
#pragma unroll
                for (int ks = 0; ks < 4; ks++) {
                    const int qw = ks * 8;
                    uint32_t ah[4], al[4], bfr[2][4], blr[2][4];
                    {
                        int row = rt * 16 + a_r;
                        uint32_t aaddr = sq_b +
                            (uint32_t)(row * 32 + swz(qw + a_w, row)) * 4;
                        ldsm4(ah, aaddr);
                        ldsm4(al, aaddr + 1024 * 4);
                    }
#pragma unroll
                    for (int np = 0; np < 2; np++) {
                        int tok = ct * 32 + np * 16 + b_r;
                        uint32_t baddr = kbb +
                            (uint32_t)(tok * 32 + swz(qw + b_w, tok)) * 4;
                        ldsm4(bfr[np], baddr);
                        ldsm4(blr[np], baddr + 4096 * 4);
                    }
#pragma unroll
                    for (int nf = 0; nf < 4; nf++) {
                        const uint32_t* bhv = &bfr[nf >> 1][(nf & 1) * 2];
                        const uint32_t* blv = &blr[nf >> 1][(nf & 1) * 2];
                        mma16(accp[nf], ah, bhv);
                        mma16(accp[nf], ah, blv);
                        mma16(accp[nf], al, bhv);
                    }
                }
#pragma unroll
                for (int nf = 0; nf < 4; nf++) {
                    int col = cb + ct * 32 + nf * 8 + 2 * t;
                    *(float2*)&sS[(rt * 16 + g) * SS_STR + col] =
                        make_float2(accp[nf][0], accp[nf][1]);
                    *(float2*)&sS[(rt * 16 + 8 + g) * SS_STR + col] =
                        make_float2(accp[nf][2], accp[nf][3]);
                }
            }
            __syncthreads();
        }

        // ---------------- consumer: two passes of 16 rows ----------------
        if (mode < 2) {
#pragma unroll
            for (int p = 0; p < 2; p++) {
                const int lro = p * 16 + qg * 4;
                const int qminp = q0 + lro;
                const bool skipc = (mode == 0 && c_lo > qminp + 3) ||
                                   (mode == 1 && c_hi < qminp);
                float acc[4][8];
                float tval[4];
#pragma unroll
                for (int r = 0; r < 4; r++) {
                    if (skipc) {
#pragma unroll
                        for (int c = 0; c < 8; c++) acc[r][c] = 0.0f;
                        tval[r] = 0.0f;
                        if (lane == 31) sRed[(qg * 4 + r) * 2 + half] = 0.0f;
                    } else {
                        const float* srow = &sS[(lro + r) * SS_STR + kg * 8];
                        float4 s0 = *(const float4*)&srow[0];
                        float4 s1 = *(const float4*)&srow[4];
                        acc[r][0] = s0.x; acc[r][1] = s0.y; acc[r][2] = s0.z; acc[r][3] = s0.w;
                        acc[r][4] = s1.x; acc[r][5] = s1.y; acc[r][6] = s1.z; acc[r][7] = s1.w;
                        int q = qminp + r;
                        if (mode == 0) {
#pragma unroll
                            for (int c = 0; c < 8; c++)
                                if (kg * 8 + c > q) acc[r][c] = -1.0e9f;
                        } else {
#pragma unroll
                            for (int c = 0; c < 8; c++)
                                if (kg * 8 + c < q) acc[r][c] = -1.0e9f;
                        }
                        float run = 0.0f;
#pragma unroll
                        for (int c = 0; c < 8; c++) {
                            run += __expf(acc[r][c]);
                            acc[r][c] = run;
                        }
                        float tv = run;
#pragma unroll
                        for (int off = 1; off < 32; off <<= 1) {
                            float u = __shfl_up_sync(0xffffffffu, tv, off);
                            if (lane >= off) tv += u;
                        }
                        tval[r] = tv;
                        if (lane == 31) sRed[(qg * 4 + r) * 2 + half] = tv;
                    }
                }
                __syncthreads();
#pragma unroll
                for (int r = 0; r < 4; r++) {
                    float w0 = sRed[(qg * 4 + r) * 2 + 0], w1 = sRed[(qg * 4 + r) * 2 + 1];
                    float sumrow = w0 + w1;
                    float tot = acc[r][7];
                    float excl = (half ? w0 : 0.0f) + (tval[r] - tot);
                    float inv = 1.0f / sumrow;
                    float* mrow_p = &sMK[(lro + r) * 512 + kg * 8];
                    if (mode == 0) {
                        float v[8];
#pragma unroll
                        for (int c = 0; c < 8; c++)
                            v[c] = (excl + acc[r][c]) * inv;
                        *(float4*)&mrow_p[0] = make_float4(v[0], v[1], v[2], v[3]);
                        *(float4*)&mrow_p[4] = make_float4(v[4], v[5], v[6], v[7]);
                    } else {
                        float4 m0 = *(const float4*)&mrow_p[0];
                        float4 m1 = *(const float4*)&mrow_p[4];
                        float m[8] = {m0.x, m0.y, m0.z, m0.w, m1.x, m1.y, m1.z, m1.w};
                        float base = sumrow - excl;
                        m[0] *= base * inv;
#pragma unroll
                        for (int c = 1; c < 8; c++)
                            m[c] *= (base - acc[r][c - 1]) * inv;
                        *(float4*)&mrow_p[0] = make_float4(m[0], m[1], m[2], m[3]);
                        *(float4*)&mrow_p[4] = make_float4(m[4], m[5], m[6], m[7]);
                    }
                }
                __syncthreads();
            }
        } else {
            float lsum = 0.0f;
#pragma unroll
            for (int p = 0; p < 2; p++) {
                const int lro = p * 16 + qg * 4;
                const int qminp = q0 + lro;
                float acc[4][8];
#pragma unroll
                for (int r = 0; r < 4; r++) {
                    const float* srow = &sS[(lro + r) * SS_STR + kg * 8];
                    float4 s0 = *(const float4*)&srow[0];
                    float4 s1 = *(const float4*)&srow[4];
                    acc[r][0] = s0.x; acc[r][1] = s0.y; acc[r][2] = s0.z; acc[r][3] = s0.w;
                    acc[r][4] = s1.x; acc[r][5] = s1.y; acc[r][6] = s1.z; acc[r][7] = s1.w;
                    const float* mrow_p = &sMK[(lro + r) * 512 + kg * 8];
                    float4 m0 = *(const float4*)&mrow_p[0];
                    float4 m1 = *(const float4*)&mrow_p[4];
                    float m[8] = {m0.x, m0.y, m0.z, m0.w, m1.x, m1.y, m1.z, m1.w};
#pragma unroll
                    for (int c = 0; c < 8; c++)
                        acc[r][c] = (acc[r][c] - rmq[p][r] - rmk[c]) * m[c];
                }
                float mrow[4];
#pragma unroll
                for (int r = 0; r < 4; r++) {
                    float m = acc[r][0];
#pragma unroll
                    for (int c = 1; c < 8; c++) m = fmaxf(m, acc[r][c]);
#pragma unroll
                    for (int off = 16; off >= 1; off >>= 1)
                        m = fmaxf(m, __shfl_xor_sync(0xffffffffu, m, off));
                    if (lane == 0) sRed[(qg * 4 + r) * 2 + half] = m;
                }
                __syncthreads();
#pragma unroll
                for (int r = 0; r < 4; r++)
                    mrow[r] = fmaxf(sRed[(qg * 4 + r) * 2 + 0], sRed[(qg * 4 + r) * 2 + 1]);
                __syncthreads();

#pragma unroll
                for (int r = 0; r < 4; r++) {
                    float s = 0.0f;
#pragma unroll
                    for (int c = 0; c < 8; c++) {
                        acc[r][c] = __expf(acc[r][c] - mrow[r]);
                        s += acc[r][c];
                    }
#pragma unroll
                    for (int off = 16; off >= 1; off >>= 1)
                        s += __shfl_xor_sync(0xffffffffu, s, off);
                    if (lane == 0) sRed[(qg * 4 + r) * 2 + half] = s;
                }
                __syncthreads();
#pragma unroll
                for (int r = 0; r < 4; r++) {
                    int q = qminp + r;
                    float inv = 1.0f / (sRed[(qg * 4 + r) * 2 + 0] + sRed[(qg * 4 + r) * 2 + 1]);
                    size_t oidx = ((size_t)bh * Sq + q) * Sq + kg * 8;
                    size_t sidx = ((size_t)((h * Bq + b) * Sq + q)) * Sq + kg * 8;
                    float4 sp0 = *(const float4*)&span[sidx];
                    float4 sp1 = *(const float4*)&span[sidx + 4];
                    float sp[8] = {sp0.x, sp0.y, sp0.z, sp0.w, sp1.x, sp1.y, sp1.z, sp1.w};
                    float pv[8];
#pragma unroll
                    for (int c = 0; c < 8; c++) pv[c] = acc[r][c] * inv;
                    float4 o0 = {pv[0], pv[1], pv[2], pv[3]};
                    float4 o1 = {pv[4], pv[5], pv[6], pv[7]};
                    *(float4*)&out[oidx]     = o0;
                    *(float4*)&out[oidx + 4] = o1;
#pragma unroll
                    for (int c = 0; c < 8; c++)
                        lsum += softplus_neg01(pv[c]) + pv[c] * (1.0f - sp[c]);
                }
                __syncthreads();
            }
#pragma unroll
            for (int off = 16; off >= 1; off >>= 1)
                lsum += __shfl_xor_sync(0xffffffffu, lsum, off);
            if (lane == 0) sW[warp] = lsum;
            __syncthreads();
            if (tid == 0) {
                float tot = 0.0f;
#pragma unroll
                for (int ww = 0; ww < 8; ww++) tot += sW[ww];
                atomicAdd(&g_loss, (double)tot);
            }
        }
    }
}

__global__ void finalize_kernel(float* out, int out_size) {
    if (out_size > NATT)
        out[NATT] = (float)(g_loss / (double)NATT);
}

// ---------------------------------------------------------------------------
extern "C" void kernel_launch(void* const* d_in, const int* in_sizes, int n_in,
                              void* d_out, int out_size)
{
    (void)in_sizes; (void)n_in;
    const float* query = (const float*)d_in[0];
    const float* key   = (const float*)d_in[1];
    const float* mask  = (const float*)d_in[2];
    const float* span  = (const float*)d_in[3];
    float* out = (float*)d_out;

    Ptr6 ws, bs;
    for (int w = 0; w < 6; w++) {
        ws.p[w] = (const float*)d_in[4 + 2 * w];
        bs.p[w] = (const float*)d_in[5 + 2 * w];
    }

    cudaFuncSetAttribute(gemm_mma, cudaFuncAttributeMaxDynamicSharedMemorySize, DYN_SMEM);
    cudaFuncSetAttribute(attn_fused, cudaFuncAttributeMaxDynamicSharedMemorySize, ATTN_SMEM_BYTES);

    pack_qk<<<dim3(Mrows * PW / 256, 2), 256>>>(query, key);
    transpose_pack6<<<dim3(Dm / 32, Dm / 32, 6), dim3(32, 8)>>>(ws);
    gemm_mma<<<dim3(Mrows / BM, Dm / BN, 6), 256, DYN_SMEM>>>(bs);
    attn_fused<<<dim3(Sq / QROWS, BHn), 256, ATTN_SMEM_BYTES>>>(mask, span, out);
    finalize_kernel<<<1, 1>>>(out, out_size);
}

// round 15
// speedup vs baseline: 1.4566x; 1.4566x over previous
#include <cuda_runtime.h>
#include <cstdint>
#include <math.h>

#define Bq    8
#define Sq    512
#define Dm    768
#define Hh    12
#define Dk    64
#define BHn   (Bq*Hh)            // 96
#define Mrows (Bq*Sq)            // 4096
#define NATT  (25165824)         // B*H*S*S
#define SCALE 0.036084391824351615f   // 1/sqrt(768)
#define PW    384                // packed words per row (Dm/2)

// ---- projection GEMM tiling (bf16 m16n8k16, 3x split) ----
#define BM 128
#define BN 128
#define APL 2560                 // A plane words per stage: 128*20
#define BPL 2560                 // B plane words per stage: 128*20
#define STAGE_W (2*APL + 2*BPL)  // 10240 words
#define DYN_SMEM (2*STAGE_W*4)   // 81920 bytes
#define NSTAGE (Dm/32)           // 24

// ---- attn smem layout (4B words), 32 q-rows per block ----
#define QROWS 32
#define KBUF  9216               // K chunk buffer: 2 planes x 128 tok x 36 words
#define SS_STR 520
#define OFF_SQ   0                               // 2 planes x 32 x 36 = 2304
#define OFF_SKB  2304                            // 2 bufs x 9216 = 18432
#define OFF_SS   20736                           // 32 x 520 = 16640
#define OFF_SMK  37376                           // 32 x 512 = 16384
#define OFF_RED  53760                           // 32
#define OFF_W    53792                           // 8
#define ATTN_SMEM_BYTES  ((OFF_W + 8)*4)         // 215200

// Scratch (device globals: allocation-free, graph-capturable)
__device__ uint32_t g_qkP[(size_t)2 * 2 * Mrows * PW];   // [mat][plane] query,key packed
__device__ uint32_t g_wP[(size_t)6 * 2 * Dm * PW];       // [w][plane] W^T packed
__device__ uint32_t g_projP[(size_t)6 * 2 * Mrows * PW]; // [w][plane] projections packed
__device__ double g_loss;

struct Ptr6 { const float* p[6]; };

// ---------------------------------------------------------------------------
// helpers
// ---------------------------------------------------------------------------
__device__ __forceinline__ uint32_t smem_u32(const void* p) {
    uint32_t a;
    asm("{ .reg .u64 t; cvta.to.shared.u64 t, %1; cvt.u32.u64 %0, t; }"
        : "=r"(a) : "l"(p));
    return a;
}
__device__ __forceinline__ void cp16(uint32_t s, const void* g) {
    asm volatile("cp.async.ca.shared.global [%0], [%1], 16;"
                 :: "r"(s), "l"(g) : "memory");
}
__device__ __forceinline__ void cp_commit() {
    asm volatile("cp.async.commit_group;" ::: "memory");
}
template <int N>
__device__ __forceinline__ void cp_wait() {
    asm volatile("cp.async.wait_group %0;" :: "n"(N) : "memory");
}
// ldmatrix x4: one instr loads 4 fragment registers
__device__ __forceinline__ void ldsm4(uint32_t* r, uint32_t addr) {
    asm volatile("ldmatrix.sync.aligned.m8n8.x4.shared.b16 {%0,%1,%2,%3}, [%4];"
        : "=r"(r[0]), "=r"(r[1]), "=r"(r[2]), "=r"(r[3]) : "r"(addr));
}
// bf16 hi/lo split (bit ops only; Sterbenz => a-hi exact)
__device__ __forceinline__ void splitb(float a, uint32_t& hb, uint32_t& lb) {
    uint32_t u = __float_as_uint(a);
    hb = u & 0xFFFF0000u;
    float l = a - __uint_as_float(hb);
    lb = __float_as_uint(l) & 0xFFFF0000u;
}
__device__ __forceinline__ uint32_t packw(uint32_t b0, uint32_t b1) {
    return b1 | (b0 >> 16);
}
__device__ __forceinline__ void mma16(float* c, const uint32_t* a, const uint32_t* b) {
    asm volatile(
        "mma.sync.aligned.m16n8k16.row.col.f32.bf16.bf16.f32 "
        "{%0,%1,%2,%3}, {%4,%5,%6,%7}, {%8,%9}, {%0,%1,%2,%3};"
        : "+f"(c[0]), "+f"(c[1]), "+f"(c[2]), "+f"(c[3])
        : "r"(a[0]), "r"(a[1]), "r"(a[2]), "r"(a[3]), "r"(b[0]), "r"(b[1]));
}
// ln(1+e^-p) for p in [0,1], no MUFU (Taylor, err ~1.5e-8)
__device__ __forceinline__ float softplus_neg01(float p) {
    float x = 0.5f * p;
    float y = x * x;
    float lc = y * (0.5f + y * (-8.3333333333e-2f + y * (2.2222222222e-2f +
               y * (-6.7460317460e-3f + y * (2.1869488536e-3f +
               y * (-7.3860295563e-4f))))));
    return 0.69314718056f - x + lc;
}

// ---------------------------------------------------------------------------
// Pack query/key into bf16 hi/lo planes (also zeroes g_loss).
// ---------------------------------------------------------------------------
__global__ void pack_qk(const float* __restrict__ query, const float* __restrict__ key) {
    if (blockIdx.x == 0 && blockIdx.y == 0 && threadIdx.x == 0) g_loss = 0.0;
    int mat = blockIdx.y;
    const float* src = mat ? key : query;
    uint32_t* hi = g_qkP + (size_t)(mat * 2 + 0) * Mrows * PW;
    uint32_t* lo = g_qkP + (size_t)(mat * 2 + 1) * Mrows * PW;
    int idx = blockIdx.x * 256 + threadIdx.x;
    float2 v = *(const float2*)&src[(size_t)idx * 2];
    uint32_t h0, l0, h1, l1;
    splitb(v.x, h0, l0);
    splitb(v.y, h1, l1);
    hi[idx] = packw(h0, h1);
    lo[idx] = packw(l0, l1);
}

// ---------------------------------------------------------------------------
// Transpose + pack all 6 weight matrices as bf16 hi/lo planes (n-major).
// ---------------------------------------------------------------------------
__global__ void transpose_pack6(Ptr6 ws) {
    __shared__ float t[32][33];
    int w = blockIdx.z;
    const float* W = ws.p[w];
    uint32_t* Thi = g_wP + (size_t)(w * 2 + 0) * Dm * PW;
    uint32_t* Tlo = g_wP + (size_t)(w * 2 + 1) * Dm * PW;
    int n0 = blockIdx.x * 32, k0 = blockIdx.y * 32;
    int tid = threadIdx.y * 32 + threadIdx.x;
#pragma unroll
    for (int i = 0; i < 4; i++)
        t[threadIdx.y + i * 8][threadIdx.x] =
            W[(size_t)(k0 + threadIdx.y + i * 8) * Dm + n0 + threadIdx.x];
    __syncthreads();
#pragma unroll
    for (int i = 0; i < 2; i++) {
        int lin = i * 256 + tid;
        int n = lin >> 4, j = lin & 15;
        uint32_t h0, l0, h1, l1;
        splitb(t[2 * j][n],     h0, l0);
        splitb(t[2 * j + 1][n], h1, l1);
        size_t idx = (size_t)(n0 + n) * PW + k0 / 2 + j;
        Thi[idx] = packw(h0, h1);
        Tlo[idx] = packw(l0, l1);
    }
}

// ---------------------------------------------------------------------------
// bf16 m16n8k16 GEMM (3x split), ldmatrix fragment loads, BN=128.
// grid (32 m, 6 n, 6 gemms), 256 threads, cp.async double-buffered.
// ---------------------------------------------------------------------------
__global__ __launch_bounds__(256, 2) void gemm_mma(Ptr6 biases)
{
    extern __shared__ uint32_t dsw[];
    const int tid = threadIdx.x, warp = tid >> 5, lane = tid & 31;
    const int g = lane >> 2, t = lane & 3;
    const int wm = (warp >> 1) * 32, wn = (warp & 1) * 64;
    const int a_r = ((lane >> 3) & 1) * 8 + (lane & 7);
    const int a_w = (lane >> 4) * 4;
    const int b_r = (lane >> 4) * 8 + (lane & 7);
    const int b_w = ((lane >> 3) & 1) * 4;

    const int w = blockIdx.z;
    const int mat = w & 1;
    const uint32_t* Asrc = g_qkP + (size_t)(mat * 2) * Mrows * PW;
    const uint32_t* Bsrc = g_wP + (size_t)(w * 2) * Dm * PW;
    uint32_t* Phi = g_projP + (size_t)(w * 2 + 0) * Mrows * PW;
    uint32_t* Plo = g_projP + (size_t)(w * 2 + 1) * Mrows * PW;
    const float* bias = biases.p[w];
    const float scale = mat ? 1.0f : SCALE;
    const int m0 = blockIdx.x * BM, n0 = blockIdx.y * BN;

    const uint32_t sb = smem_u32(dsw);

    auto load_stage = [&](int s, int buf) {
        const int kw = s * 16;
        const uint32_t base = sb + (uint32_t)buf * STAGE_W * 4;
#pragma unroll
        for (int i = 0; i < 4; i++) {      // A: 2 planes x 128 rows x 16 words
            int id = i * 256 + tid;
            int plane = id >> 9, rem = id & 511;
            int row = rem >> 2, q = rem & 3;
            cp16(base + (uint32_t)(plane * APL + row * 20 + q * 4) * 4,
                 &Asrc[(size_t)plane * Mrows * PW + (size_t)(m0 + row) * PW + kw + q * 4]);
        }
#pragma unroll
        for (int i = 0; i < 4; i++) {      // B: 2 planes x 128 rows x 16 words
            int id = i * 256 + tid;
            int plane = id >> 9, rem = id & 511;
            int row = rem >> 2, q = rem & 3;
            cp16(base + (uint32_t)(2 * APL + plane * BPL + row * 20 + q * 4) * 4,
                 &Bsrc[(size_t)plane * Dm * PW + (size_t)(n0 + row) * PW + kw + q * 4]);
        }
        cp_commit();
    };

    float acc[2][8][4];
#pragma unroll
    for (int mf = 0; mf < 2; mf++)
#pragma unroll
        for (int nf = 0; nf < 8; nf++)
#pragma unroll
            for (int i = 0; i < 4; i++) acc[mf][nf][i] = 0.0f;

    load_stage(0, 0);

    for (int s = 0; s < NSTAGE; s++) {
        if (s + 1 < NSTAGE) { load_stage(s + 1, (s + 1) & 1); cp_wait<1>(); }
        else                { cp_wait<0>(); }
        __syncthreads();

        const uint32_t st_b = sb + (uint32_t)(s & 1) * STAGE_W * 4;

#pragma unroll
        for (int ks = 0; ks < 2; ks++) {
            const int kw = ks * 8;
            uint32_t ah[2][4], al[2][4];
#pragma unroll
            for (int mf = 0; mf < 2; mf++) {
                uint32_t aaddr = st_b +
                    (uint32_t)((wm + mf * 16 + a_r) * 20 + kw + a_w) * 4;
                ldsm4(ah[mf], aaddr);
                ldsm4(al[mf], aaddr + APL * 4);
            }
#pragma unroll
            for (int np = 0; np < 4; np++) {   // one np's B frags live at a time
                uint32_t bfr[4], blr[4];
                uint32_t baddr = st_b + (uint32_t)(2 * APL) * 4 +
                    (uint32_t)((wn + np * 16 + b_r) * 20 + kw + b_w) * 4;
                ldsm4(bfr, baddr);
                ldsm4(blr, baddr + BPL * 4);
#pragma unroll
                for (int mf = 0; mf < 2; mf++)
#pragma unroll
                    for (int sfn = 0; sfn < 2; sfn++) {
                        int nf = np * 2 + sfn;
                        mma16(acc[mf][nf], ah[mf], &bfr[sfn * 2]);
                        mma16(acc[mf][nf], ah[mf], &blr[sfn * 2]);
                        mma16(acc[mf][nf], al[mf], &bfr[sfn * 2]);
                    }
            }
        }
        __syncthreads();
    }

#pragma unroll
    for (int mf = 0; mf < 2; mf++) {
        int row0 = m0 + wm + mf * 16 + g;
#pragma unroll
        for (int nf = 0; nf < 8; nf++) {
            int col = n0 + wn + nf * 8 + 2 * t;
            int wcol = (n0 + wn + nf * 8) / 2 + t;
            float2 bv = *(const float2*)&bias[col];
            float v00 = (acc[mf][nf][0] + bv.x) * scale;
            float v01 = (acc[mf][nf][1] + bv.y) * scale;
            float v10 = (acc[mf][nf][2] + bv.x) * scale;
            float v11 = (acc[mf][nf][3] + bv.y) * scale;
            uint32_t h0, l0, h1, l1;
            splitb(v00, h0, l0); splitb(v01, h1, l1);
            Phi[(size_t)row0 * PW + wcol] = packw(h0, h1);
            Plo[(size_t)row0 * PW + wcol] = packw(l0, l1);
            splitb(v10, h0, l0); splitb(v11, h1, l1);
            Phi[(size_t)(row0 + 8) * PW + wcol] = packw(h0, h1);
            Plo[(size_t)(row0 + 8) * PW + wcol] = packw(l0, l1);
        }
    }
}

// ---------------------------------------------------------------------------
// Fused attention: 32 q-rows per block, token-chunked K staging, chunk
// skipping, smk in smem, two-pass consumer. ldmatrix fragment loads.
// (Exact R13 version — best measured.)
// ---------------------------------------------------------------------------
__global__ __launch_bounds__(256) void attn_fused(
    const float* __restrict__ mask,
    const float* __restrict__ span, float* __restrict__ out)
{
    extern __shared__ uint32_t smw[];
    uint32_t* sQ  = smw + OFF_SQ;
    uint32_t* sKB = smw + OFF_SKB;
    float* sS  = (float*)(smw + OFF_SS);
    float* sMK = (float*)(smw + OFF_SMK);
    float* sRed= (float*)(smw + OFF_RED);
    float* sW  = (float*)(smw + OFF_W);

    int tid  = threadIdx.x;
    int lane = tid & 31;
    int warp = tid >> 5;        // 0..7
    int g    = lane >> 2, t = lane & 3;
    int rt   = warp >> 2;       // producer row tile (0/1)
    int ct   = warp & 3;        // producer 32-col tile within 128-token chunk
    int half = (tid >> 5) & 1;  // consumer: which 256-col half
    int qg   = tid >> 6;        // consumer: 0..3 -> q-group (4 rows / pass)
    int kg   = tid & 63;        // consumer: 8 consecutive cols each
    const int a_r = ((lane >> 3) & 1) * 8 + (lane & 7);
    const int a_w = (lane >> 4) * 4;
    const int b_r = (lane >> 4) * 8 + (lane & 7);
    const int b_w = ((lane >> 3) & 1) * 4;

    int bh = blockIdx.y;
    int b = bh / Hh, h = bh % Hh;
    int q0 = blockIdx.x * QROWS;

    const int c_lo = half * 256, c_hi = c_lo + 255;

    float rmk[8], rmq[2][4];
#pragma unroll
    for (int c = 0; c < 8; c++) {
        float mv = mask[b * Sq + kg * 8 + c];
        rmk[c] = (mv == -10000.0f) ? 1.0e9f : mv;
    }
#pragma unroll
    for (int p = 0; p < 2; p++)
#pragma unroll
        for (int r = 0; r < 4; r++) {
            float mv = mask[b * Sq + q0 + p * 16 + qg * 4 + r];
            rmq[p][r] = (mv == -10000.0f) ? 1.0e9f : mv;
        }

    const uint32_t sq_b  = smem_u32(sQ);
    const uint32_t skb_b = smem_u32(sKB);

    for (int mode = 0; mode < 3; mode++) {
        const uint32_t* Qp = g_projP + (size_t)((mode * 2) * 2)     * Mrows * PW;
        const uint32_t* Kp = g_projP + (size_t)((mode * 2 + 1) * 2) * Mrows * PW;

        int tc_lo, tc_hi;
        if (mode == 0)      { tc_lo = 0;         tc_hi = (q0 + 31) / 128 + 1; }
        else if (mode == 1) { tc_lo = q0 >> 7;   tc_hi = 4; }
        else                { tc_lo = 0;         tc_hi = 4; }

        auto stageK = [&](int tc, int buf) {
            const uint32_t kb = skb_b + (uint32_t)(buf * KBUF) * 4;
#pragma unroll
            for (int i = 0; i < 8; i++) {
                int id = i * 256 + tid;
                int tokl = id >> 4;
                int rem = id & 15;
                int plane = rem >> 3;
                int qw = (rem & 7) * 4;
                cp16(kb + (uint32_t)(plane * 4608 + tokl * 36 + qw) * 4,
                     &Kp[(size_t)plane * Mrows * PW +
                         (size_t)(b * Sq + tc * 128 + tokl) * PW + h * 32 + qw]);
            }
            cp_commit();
        };

        __syncthreads();   // protect sQ/sS reuse from previous mode
        {
#pragma unroll
            for (int i = 0; i < 2; i++) {
                int id = i * 256 + tid;
                int plane = id >> 8, rem = id & 255;
                int row = rem >> 3, qw = (rem & 7) * 4;
                cp16(sq_b + (uint32_t)(plane * 1152 + row * 36 + qw) * 4,
                     &Qp[(size_t)plane * Mrows * PW +
                         (size_t)(b * Sq + q0 + row) * PW + h * 32 + qw]);
            }
        }
        stageK(tc_lo, 0);

        for (int tc = tc_lo; tc < tc_hi; tc++) {
            const int bufc = (tc - tc_lo) & 1;
            if (tc + 1 < tc_hi) { stageK(tc + 1, bufc ^ 1); cp_wait<1>(); }
            else                { cp_wait<0>(); }
            __syncthreads();

            const int cb = tc * 128;
            const bool warp_do =
                (mode == 0) ? (cb + ct * 32 <= q0 + 31) :
                (mode == 1) ? (cb + ct * 32 + 31 >= q0) : true;
            if (warp_do) {
                float accp[4][4];
#pragma unroll
                for (int nf = 0; nf < 4; nf++)
#pragma unroll
                    for (int i = 0; i < 4; i++) accp[nf][i] = 0.0f;
                const uint32_t kbb = skb_b + (uint32_t)(bufc * KBUF) * 4;
#pragma unroll
                for (int ks = 0; ks < 4; ks++) {
                    const int qw = ks * 8;
                    uint32_t ah[4], al[4], bfr[2][4], blr[2][4];
                    uint32_t aaddr = sq_b +
                        (uint32_t)((rt * 16 + a_r) * 36 + qw + a_w) * 4;
                    ldsm4(ah, aaddr);
                    ldsm4(al, aaddr + 1152 * 4);
#pragma unroll
                    for (int np = 0; np < 2; np++) {
                        uint32_t baddr = kbb +
                            (uint32_t)((ct * 32 + np * 16 + b_r) * 36 + qw + b_w) * 4;
                        ldsm4(bfr[np], baddr);
                        ldsm4(blr[np], baddr + 4608 * 4);
                    }
#pragma unroll
                    for (int nf = 0; nf < 4; nf++) {
                        const uint32_t* bhv = &bfr[nf >> 1][(nf & 1) * 2];
                        const uint32_t* blv = &blr[nf >> 1][(nf & 1) * 2];
                        mma16(accp[nf], ah, bhv);
                        mma16(accp[nf], ah, blv);
                        mma16(accp[nf], al, bhv);
                    }
                }
#pragma unroll
                for (int nf = 0; nf < 4; nf++) {
                    int col = cb + ct * 32 + nf * 8 + 2 * t;
                    *(float2*)&sS[(rt * 16 + g) * SS_STR + col] =
                        make_float2(accp[nf][0], accp[nf][1]);
                    *(float2*)&sS[(rt * 16 + 8 + g) * SS_STR + col] =
                        make_float2(accp[nf][2], accp[nf][3]);
                }
            }
            __syncthreads();
        }

        // ---------------- consumer: two passes of 16 rows ----------------
        if (mode < 2) {
#pragma unroll
            for (int p = 0; p < 2; p++) {
                const int lro = p * 16 + qg * 4;
                const int qminp = q0 + lro;
                const bool skipc = (mode == 0 && c_lo > qminp + 3) ||
                                   (mode == 1 && c_hi < qminp);
                float acc[4][8];
                float tval[4];
#pragma unroll
                for (int r = 0; r < 4; r++) {
                    if (skipc) {
#pragma unroll
                        for (int c = 0; c < 8; c++) acc[r][c] = 0.0f;
                        tval[r] = 0.0f;
                        if (lane == 31) sRed[(qg * 4 + r) * 2 + half] = 0.0f;
                    } else {
                        const float* srow = &sS[(lro + r) * SS_STR + kg * 8];
                        float4 s0 = *(const float4*)&srow[0];
                        float4 s1 = *(const float4*)&srow[4];
                        acc[r][0] = s0.x; acc[r][1] = s0.y; acc[r][2] = s0.z; acc[r][3] = s0.w;
                        acc[r][4] = s1.x; acc[r][5] = s1.y; acc[r][6] = s1.z; acc[r][7] = s1.w;
                        int q = qminp + r;
                        if (mode == 0) {
#pragma unroll
                            for (int c = 0; c < 8; c++)
                                if (kg * 8 + c > q) acc[r][c] = -1.0e9f;
                        } else {
#pragma unroll
                            for (int c = 0; c < 8; c++)
                                if (kg * 8 + c < q) acc[r][c] = -1.0e9f;
                        }
                        float run = 0.0f;
#pragma unroll
                        for (int c = 0; c < 8; c++) {
                            run += __expf(acc[r][c]);
                            acc[r][c] = run;
                        }
                        float tv = run;
#pragma unroll
                        for (int off = 1; off < 32; off <<= 1) {
                            float u = __shfl_up_sync(0xffffffffu, tv, off);
                            if (lane >= off) tv += u;
                        }
                        tval[r] = tv;
                        if (lane == 31) sRed[(qg * 4 + r) * 2 + half] = tv;
                    }
                }
                __syncthreads();
#pragma unroll
                for (int r = 0; r < 4; r++) {
                    float w0 = sRed[(qg * 4 + r) * 2 + 0], w1 = sRed[(qg * 4 + r) * 2 + 1];
                    float sumrow = w0 + w1;
                    float tot = acc[r][7];
                    float excl = (half ? w0 : 0.0f) + (tval[r] - tot);
                    float inv = 1.0f / sumrow;
                    float* mrow_p = &sMK[(lro + r) * 512 + kg * 8];
                    if (mode == 0) {
                        float v[8];
#pragma unroll
                        for (int c = 0; c < 8; c++)
                            v[c] = (excl + acc[r][c]) * inv;
                        *(float4*)&mrow_p[0] = make_float4(v[0], v[1], v[2], v[3]);
                        *(float4*)&mrow_p[4] = make_float4(v[4], v[5], v[6], v[7]);
                    } else {
                        float4 m0 = *(const float4*)&mrow_p[0];
                        float4 m1 = *(const float4*)&mrow_p[4];
                        float m[8] = {m0.x, m0.y, m0.z, m0.w, m1.x, m1.y, m1.z, m1.w};
                        float base = sumrow - excl;
                        m[0] *= base * inv;
#pragma unroll
                        for (int c = 1; c < 8; c++)
                            m[c] *= (base - acc[r][c - 1]) * inv;
                        *(float4*)&mrow_p[0] = make_float4(m[0], m[1], m[2], m[3]);
                        *(float4*)&mrow_p[4] = make_float4(m[4], m[5], m[6], m[7]);
                    }
                }
                __syncthreads();
            }
        } else {
            float lsum = 0.0f;
#pragma unroll
            for (int p = 0; p < 2; p++) {
                const int lro = p * 16 + qg * 4;
                const int qminp = q0 + lro;
                float acc[4][8];
#pragma unroll
                for (int r = 0; r < 4; r++) {
                    const float* srow = &sS[(lro + r) * SS_STR + kg * 8];
                    float4 s0 = *(const float4*)&srow[0];
                    float4 s1 = *(const float4*)&srow[4];
                    acc[r][0] = s0.x; acc[r][1] = s0.y; acc[r][2] = s0.z; acc[r][3] = s0.w;
                    acc[r][4] = s1.x; acc[r][5] = s1.y; acc[r][6] = s1.z; acc[r][7] = s1.w;
                    const float* mrow_p = &sMK[(lro + r) * 512 + kg * 8];
                    float4 m0 = *(const float4*)&mrow_p[0];
                    float4 m1 = *(const float4*)&mrow_p[4];
                    float m[8] = {m0.x, m0.y, m0.z, m0.w, m1.x, m1.y, m1.z, m1.w};
#pragma unroll
                    for (int c = 0; c < 8; c++)
                        acc[r][c] = (acc[r][c] - rmq[p][r] - rmk[c]) * m[c];
                }
                float mrow[4];
#pragma unroll
                for (int r = 0; r < 4; r++) {
                    float m = acc[r][0];
#pragma unroll
                    for (int c = 1; c < 8; c++) m = fmaxf(m, acc[r][c]);
#pragma unroll
                    for (int off = 16; off >= 1; off >>= 1)
                        m = fmaxf(m, __shfl_xor_sync(0xffffffffu, m, off));
                    if (lane == 0) sRed[(qg * 4 + r) * 2 + half] = m;
                }
                __syncthreads();
#pragma unroll
                for (int r = 0; r < 4; r++)
                    mrow[r] = fmaxf(sRed[(qg * 4 + r) * 2 + 0], sRed[(qg * 4 + r) * 2 + 1]);
                __syncthreads();

#pragma unroll
                for (int r = 0; r < 4; r++) {
                    float s = 0.0f;
#pragma unroll
                    for (int c = 0; c < 8; c++) {
                        acc[r][c] = __expf(acc[r][c] - mrow[r]);
                        s += acc[r][c];
                    }
#pragma unroll
                    for (int off = 16; off >= 1; off >>= 1)
                        s += __shfl_xor_sync(0xffffffffu, s, off);
                    if (lane == 0) sRed[(qg * 4 + r) * 2 + half] = s;
                }
                __syncthreads();
#pragma unroll
                for (int r = 0; r < 4; r++) {
                    int q = qminp + r;
                    float inv = 1.0f / (sRed[(qg * 4 + r) * 2 + 0] + sRed[(qg * 4 + r) * 2 + 1]);
                    size_t oidx = ((size_t)bh * Sq + q) * Sq + kg * 8;
                    size_t sidx = ((size_t)((h * Bq + b) * Sq + q)) * Sq + kg * 8;
                    float4 sp0 = *(const float4*)&span[sidx];
                    float4 sp1 = *(const float4*)&span[sidx + 4];
                    float sp[8] = {sp0.x, sp0.y, sp0.z, sp0.w, sp1.x, sp1.y, sp1.z, sp1.w};
                    float pv[8];
#pragma unroll
                    for (int c = 0; c < 8; c++) pv[c] = acc[r][c] * inv;
                    float4 o0 = {pv[0], pv[1], pv[2], pv[3]};
                    float4 o1 = {pv[4], pv[5], pv[6], pv[7]};
                    *(float4*)&out[oidx]     = o0;
                    *(float4*)&out[oidx + 4] = o1;
#pragma unroll
                    for (int c = 0; c < 8; c++)
                        lsum += softplus_neg01(pv[c]) + pv[c] * (1.0f - sp[c]);
                }
                __syncthreads();
            }
#pragma unroll
            for (int off = 16; off >= 1; off >>= 1)
                lsum += __shfl_xor_sync(0xffffffffu, lsum, off);
            if (lane == 0) sW[warp] = lsum;
            __syncthreads();
            if (tid == 0) {
                float tot = 0.0f;
#pragma unroll
                for (int ww = 0; ww < 8; ww++) tot += sW[ww];
                atomicAdd(&g_loss, (double)tot);
            }
        }
    }
}

__global__ void finalize_kernel(float* out, int out_size) {
    if (out_size > NATT)
        out[NATT] = (float)(g_loss / (double)NATT);
}

// ---------------------------------------------------------------------------
extern "C" void kernel_launch(void* const* d_in, const int* in_sizes, int n_in,
                              void* d_out, int out_size)
{
    (void)in_sizes; (void)n_in;
    const float* query = (const float*)d_in[0];
    const float* key   = (const float*)d_in[1];
    const float* mask  = (const float*)d_in[2];
    const float* span  = (const float*)d_in[3];
    float* out = (float*)d_out;

    Ptr6 ws, bs;
    for (int w = 0; w < 6; w++) {
        ws.p[w] = (const float*)d_in[4 + 2 * w];
        bs.p[w] = (const float*)d_in[5 + 2 * w];
    }

    cudaFuncSetAttribute(gemm_mma, cudaFuncAttributeMaxDynamicSharedMemorySize, DYN_SMEM);
    cudaFuncSetAttribute(attn_fused, cudaFuncAttributeMaxDynamicSharedMemorySize, ATTN_SMEM_BYTES);

    pack_qk<<<dim3(Mrows * PW / 256, 2), 256>>>(query, key);
    transpose_pack6<<<dim3(Dm / 32, Dm / 32, 6), dim3(32, 8)>>>(ws);
    gemm_mma<<<dim3(Mrows / BM, Dm / BN, 6), 256, DYN_SMEM>>>(bs);
    attn_fused<<<dim3(Sq / QROWS, BHn), 256, ATTN_SMEM_BYTES>>>(mask, span, out);
    finalize_kernel<<<1, 1>>>(out, out_size);
}

// round 16
// speedup vs baseline: 1.5267x; 1.0481x over previous
#include <cuda_runtime.h>
#include <cstdint>
#include <math.h>

#define Bq    8
#define Sq    512
#define Dm    768
#define Hh    12
#define Dk    64
#define BHn   (Bq*Hh)            // 96
#define Mrows (Bq*Sq)            // 4096
#define NATT  (25165824)         // B*H*S*S
#define SCALE 0.036084391824351615f   // 1/sqrt(768)
#define PW    384                // packed words per row (Dm/2)

// ---- projection GEMM tiling (bf16 m16n8k16, 3x split) ----
#define BM 128
#define BN 128
#define APL 2560                 // A plane words per stage: 128*20
#define BPL 2560                 // B plane words per stage: 128*20
#define STAGE_W (2*APL + 2*BPL)  // 10240 words
#define DYN_SMEM (2*STAGE_W*4)   // 81920 bytes
#define NSTAGE (Dm/32)           // 24

// ---- attn smem layout (4B words), 32 q-rows per block, 512 threads ----
#define QROWS 32
#define KBUF  9216               // K chunk buffer: 2 planes x 128 tok x 36 words
#define SS_STR 520
#define OFF_SQ   0                               // 2 planes x 32 x 36 = 2304
#define OFF_SKB  2304                            // 2 bufs x 9216 = 18432
#define OFF_SS   20736                           // 32 x 520 = 16640
#define OFF_SMK  37376                           // 32 x 512 = 16384
#define OFF_RED  53760                           // 64
#define OFF_W    53824                           // 16
#define ATTN_SMEM_BYTES  ((OFF_W + 16)*4)        // 215360

// Scratch (device globals: allocation-free, graph-capturable)
__device__ uint32_t g_qkP[(size_t)2 * 2 * Mrows * PW];   // [mat][plane] query,key packed
__device__ uint32_t g_wP[(size_t)6 * 2 * Dm * PW];       // [w][plane] W^T packed
__device__ uint32_t g_projP[(size_t)6 * 2 * Mrows * PW]; // [w][plane] projections packed
__device__ double g_loss;

struct Ptr6 { const float* p[6]; };

// ---------------------------------------------------------------------------
// helpers
// ---------------------------------------------------------------------------
__device__ __forceinline__ uint32_t smem_u32(const void* p) {
    uint32_t a;
    asm("{ .reg .u64 t; cvta.to.shared.u64 t, %1; cvt.u32.u64 %0, t; }"
        : "=r"(a) : "l"(p));
    return a;
}
__device__ __forceinline__ void cp16(uint32_t s, const void* g) {
    asm volatile("cp.async.ca.shared.global [%0], [%1], 16;"
                 :: "r"(s), "l"(g) : "memory");
}
__device__ __forceinline__ void cp_commit() {
    asm volatile("cp.async.commit_group;" ::: "memory");
}
template <int N>
__device__ __forceinline__ void cp_wait() {
    asm volatile("cp.async.wait_group %0;" :: "n"(N) : "memory");
}
// ldmatrix x4: one instr loads 4 fragment registers
__device__ __forceinline__ void ldsm4(uint32_t* r, uint32_t addr) {
    asm volatile("ldmatrix.sync.aligned.m8n8.x4.shared.b16 {%0,%1,%2,%3}, [%4];"
        : "=r"(r[0]), "=r"(r[1]), "=r"(r[2]), "=r"(r[3]) : "r"(addr));
}
// bf16 hi/lo split (bit ops only; Sterbenz => a-hi exact)
__device__ __forceinline__ void splitb(float a, uint32_t& hb, uint32_t& lb) {
    uint32_t u = __float_as_uint(a);
    hb = u & 0xFFFF0000u;
    float l = a - __uint_as_float(hb);
    lb = __float_as_uint(l) & 0xFFFF0000u;
}
__device__ __forceinline__ uint32_t packw(uint32_t b0, uint32_t b1) {
    return b1 | (b0 >> 16);
}
__device__ __forceinline__ void mma16(float* c, const uint32_t* a, const uint32_t* b) {
    asm volatile(
        "mma.sync.aligned.m16n8k16.row.col.f32.bf16.bf16.f32 "
        "{%0,%1,%2,%3}, {%4,%5,%6,%7}, {%8,%9}, {%0,%1,%2,%3};"
        : "+f"(c[0]), "+f"(c[1]), "+f"(c[2]), "+f"(c[3])
        : "r"(a[0]), "r"(a[1]), "r"(a[2]), "r"(a[3]), "r"(b[0]), "r"(b[1]));
}
// ln(1+e^-p) for p in [0,1], no MUFU (Taylor, err ~1.5e-8)
__device__ __forceinline__ float softplus_neg01(float p) {
    float x = 0.5f * p;
    float y = x * x;
    float lc = y * (0.5f + y * (-8.3333333333e-2f + y * (2.2222222222e-2f +
               y * (-6.7460317460e-3f + y * (2.1869488536e-3f +
               y * (-7.3860295563e-4f))))));
    return 0.69314718056f - x + lc;
}

// ---------------------------------------------------------------------------
// Pack query/key into bf16 hi/lo planes (also zeroes g_loss).
// ---------------------------------------------------------------------------
__global__ void pack_qk(const float* __restrict__ query, const float* __restrict__ key) {
    if (blockIdx.x == 0 && blockIdx.y == 0 && threadIdx.x == 0) g_loss = 0.0;
    int mat = blockIdx.y;
    const float* src = mat ? key : query;
    uint32_t* hi = g_qkP + (size_t)(mat * 2 + 0) * Mrows * PW;
    uint32_t* lo = g_qkP + (size_t)(mat * 2 + 1) * Mrows * PW;
    int idx = blockIdx.x * 256 + threadIdx.x;
    float2 v = *(const float2*)&src[(size_t)idx * 2];
    uint32_t h0, l0, h1, l1;
    splitb(v.x, h0, l0);
    splitb(v.y, h1, l1);
    hi[idx] = packw(h0, h1);
    lo[idx] = packw(l0, l1);
}

// ---------------------------------------------------------------------------
// Transpose + pack all 6 weight matrices as bf16 hi/lo planes (n-major).
// ---------------------------------------------------------------------------
__global__ void transpose_pack6(Ptr6 ws) {
    __shared__ float t[32][33];
    int w = blockIdx.z;
    const float* W = ws.p[w];
    uint32_t* Thi = g_wP + (size_t)(w * 2 + 0) * Dm * PW;
    uint32_t* Tlo = g_wP + (size_t)(w * 2 + 1) * Dm * PW;
    int n0 = blockIdx.x * 32, k0 = blockIdx.y * 32;
    int tid = threadIdx.y * 32 + threadIdx.x;
#pragma unroll
    for (int i = 0; i < 4; i++)
        t[threadIdx.y + i * 8][threadIdx.x] =
            W[(size_t)(k0 + threadIdx.y + i * 8) * Dm + n0 + threadIdx.x];
    __syncthreads();
#pragma unroll
    for (int i = 0; i < 2; i++) {
        int lin = i * 256 + tid;
        int n = lin >> 4, j = lin & 15;
        uint32_t h0, l0, h1, l1;
        splitb(t[2 * j][n],     h0, l0);
        splitb(t[2 * j + 1][n], h1, l1);
        size_t idx = (size_t)(n0 + n) * PW + k0 / 2 + j;
        Thi[idx] = packw(h0, h1);
        Tlo[idx] = packw(l0, l1);
    }
}

// ---------------------------------------------------------------------------
// bf16 m16n8k16 GEMM (3x split), ldmatrix fragment loads, BN=128.
// grid (32 m, 6 n, 6 gemms), 256 threads, cp.async double-buffered.
// ---------------------------------------------------------------------------
__global__ __launch_bounds__(256, 2) void gemm_mma(Ptr6 biases)
{
    extern __shared__ uint32_t dsw[];
    const int tid = threadIdx.x, warp = tid >> 5, lane = tid & 31;
    const int g = lane >> 2, t = lane & 3;
    const int wm = (warp >> 1) * 32, wn = (warp & 1) * 64;
    const int a_r = ((lane >> 3) & 1) * 8 + (lane & 7);
    const int a_w = (lane >> 4) * 4;
    const int b_r = (lane >> 4) * 8 + (lane & 7);
    const int b_w = ((lane >> 3) & 1) * 4;

    const int w = blockIdx.z;
    const int mat = w & 1;
    const uint32_t* Asrc = g_qkP + (size_t)(mat * 2) * Mrows * PW;
    const uint32_t* Bsrc = g_wP + (size_t)(w * 2) * Dm * PW;
    uint32_t* Phi = g_projP + (size_t)(w * 2 + 0) * Mrows * PW;
    uint32_t* Plo = g_projP + (size_t)(w * 2 + 1) * Mrows * PW;
    const float* bias = biases.p[w];
    const float scale = mat ? 1.0f : SCALE;
    const int m0 = blockIdx.x * BM, n0 = blockIdx.y * BN;

    const uint32_t sb = smem_u32(dsw);

    auto load_stage = [&](int s, int buf) {
        const int kw = s * 16;
        const uint32_t base = sb + (uint32_t)buf * STAGE_W * 4;
#pragma unroll
        for (int i = 0; i < 4; i++) {      // A: 2 planes x 128 rows x 16 words
            int id = i * 256 + tid;
            int plane = id >> 9, rem = id & 511;
            int row = rem >> 2, q = rem & 3;
            cp16(base + (uint32_t)(plane * APL + row * 20 + q * 4) * 4,
                 &Asrc[(size_t)plane * Mrows * PW + (size_t)(m0 + row) * PW + kw + q * 4]);
        }
#pragma unroll
        for (int i = 0; i < 4; i++) {      // B: 2 planes x 128 rows x 16 words
            int id = i * 256 + tid;
            int plane = id >> 9, rem = id & 511;
            int row = rem >> 2, q = rem & 3;
            cp16(base + (uint32_t)(2 * APL + plane * BPL + row * 20 + q * 4) * 4,
                 &Bsrc[(size_t)plane * Dm * PW + (size_t)(n0 + row) * PW + kw + q * 4]);
        }
        cp_commit();
    };

    float acc[2][8][4];
#pragma unroll
    for (int mf = 0; mf < 2; mf++)
#pragma unroll
        for (int nf = 0; nf < 8; nf++)
#pragma unroll
            for (int i = 0; i < 4; i++) acc[mf][nf][i] = 0.0f;

    load_stage(0, 0);

    for (int s = 0; s < NSTAGE; s++) {
        if (s + 1 < NSTAGE) { load_stage(s + 1, (s + 1) & 1); cp_wait<1>(); }
        else                { cp_wait<0>(); }
        __syncthreads();

        const uint32_t st_b = sb + (uint32_t)(s & 1) * STAGE_W * 4;

#pragma unroll
        for (int ks = 0; ks < 2; ks++) {
            const int kw = ks * 8;
            uint32_t ah[2][4], al[2][4];
#pragma unroll
            for (int mf = 0; mf < 2; mf++) {
                uint32_t aaddr = st_b +
                    (uint32_t)((wm + mf * 16 + a_r) * 20 + kw + a_w) * 4;
                ldsm4(ah[mf], aaddr);
                ldsm4(al[mf], aaddr + APL * 4);
            }
#pragma unroll
            for (int np = 0; np < 4; np++) {   // one np's B frags live at a time
                uint32_t bfr[4], blr[4];
                uint32_t baddr = st_b + (uint32_t)(2 * APL) * 4 +
                    (uint32_t)((wn + np * 16 + b_r) * 20 + kw + b_w) * 4;
                ldsm4(bfr, baddr);
                ldsm4(blr, baddr + BPL * 4);
#pragma unroll
                for (int mf = 0; mf < 2; mf++)
#pragma unroll
                    for (int sfn = 0; sfn < 2; sfn++) {
                        int nf = np * 2 + sfn;
                        mma16(acc[mf][nf], ah[mf], &bfr[sfn * 2]);
                        mma16(acc[mf][nf], ah[mf], &blr[sfn * 2]);
                        mma16(acc[mf][nf], al[mf], &bfr[sfn * 2]);
                    }
            }
        }
        __syncthreads();
    }

#pragma unroll
    for (int mf = 0; mf < 2; mf++) {
        int row0 = m0 + wm + mf * 16 + g;
#pragma unroll
        for (int nf = 0; nf < 8; nf++) {
            int col = n0 + wn + nf * 8 + 2 * t;
            int wcol = (n0 + wn + nf * 8) / 2 + t;
            float2 bv = *(const float2*)&bias[col];
            float v00 = (acc[mf][nf][0] + bv.x) * scale;
            float v01 = (acc[mf][nf][1] + bv.y) * scale;
            float v10 = (acc[mf][nf][2] + bv.x) * scale;
            float v11 = (acc[mf][nf][3] + bv.y) * scale;
            uint32_t h0, l0, h1, l1;
            splitb(v00, h0, l0); splitb(v01, h1, l1);
            Phi[(size_t)row0 * PW + wcol] = packw(h0, h1);
            Plo[(size_t)row0 * PW + wcol] = packw(l0, l1);
            splitb(v10, h0, l0); splitb(v11, h1, l1);
            Phi[(size_t)(row0 + 8) * PW + wcol] = packw(h0, h1);
            Plo[(size_t)(row0 + 8) * PW + wcol] = packw(l0, l1);
        }
    }
}

// ---------------------------------------------------------------------------
// Fused attention: 32 q-rows per block, 512 threads (16 warps).
// Producer: 16 warps x m16n16; consumer: single pass, 8 q-groups x 4 rows.
// ---------------------------------------------------------------------------
__global__ __launch_bounds__(512) void attn_fused(
    const float* __restrict__ mask,
    const float* __restrict__ span, float* __restrict__ out)
{
    extern __shared__ uint32_t smw[];
    uint32_t* sQ  = smw + OFF_SQ;
    uint32_t* sKB = smw + OFF_SKB;
    float* sS  = (float*)(smw + OFF_SS);
    float* sMK = (float*)(smw + OFF_SMK);
    float* sRed= (float*)(smw + OFF_RED);
    float* sW  = (float*)(smw + OFF_W);

    int tid  = threadIdx.x;
    int lane = tid & 31;
    int warp = tid >> 5;        // 0..15
    int g    = lane >> 2, t = lane & 3;
    int rt   = warp >> 3;       // producer row tile (0/1)
    int ct   = warp & 7;        // producer 16-col tile within 128-token chunk
    int half = (tid >> 5) & 1;  // consumer: which 256-col half
    int qg   = tid >> 6;        // consumer: 0..7 -> q-group (4 rows)
    int kg   = tid & 63;        // consumer: 8 consecutive cols each
    const int a_r = ((lane >> 3) & 1) * 8 + (lane & 7);
    const int a_w = (lane >> 4) * 4;
    const int b_r = (lane >> 4) * 8 + (lane & 7);
    const int b_w = ((lane >> 3) & 1) * 4;

    int bh = blockIdx.y;
    int b = bh / Hh, h = bh % Hh;
    int q0 = blockIdx.x * QROWS;

    const int c_lo = half * 256, c_hi = c_lo + 255;
    const int qmin = q0 + qg * 4;

    float rmk[8], rmq[4];
#pragma unroll
    for (int c = 0; c < 8; c++) {
        float mv = mask[b * Sq + kg * 8 + c];
        rmk[c] = (mv == -10000.0f) ? 1.0e9f : mv;
    }
#pragma unroll
    for (int r = 0; r < 4; r++) {
        float mv = mask[b * Sq + qmin + r];
        rmq[r] = (mv == -10000.0f) ? 1.0e9f : mv;
    }

    const uint32_t sq_b  = smem_u32(sQ);
    const uint32_t skb_b = smem_u32(sKB);

    for (int mode = 0; mode < 3; mode++) {
        const uint32_t* Qp = g_projP + (size_t)((mode * 2) * 2)     * Mrows * PW;
        const uint32_t* Kp = g_projP + (size_t)((mode * 2 + 1) * 2) * Mrows * PW;

        int tc_lo, tc_hi;
        if (mode == 0)      { tc_lo = 0;         tc_hi = (q0 + 31) / 128 + 1; }
        else if (mode == 1) { tc_lo = q0 >> 7;   tc_hi = 4; }
        else                { tc_lo = 0;         tc_hi = 4; }

        auto stageK = [&](int tc, int buf) {
            const uint32_t kb = skb_b + (uint32_t)(buf * KBUF) * 4;
#pragma unroll
            for (int i = 0; i < 4; i++) {
                int id = i * 512 + tid;
                int tokl = id >> 4;
                int rem = id & 15;
                int plane = rem >> 3;
                int qw = (rem & 7) * 4;
                cp16(kb + (uint32_t)(plane * 4608 + tokl * 36 + qw) * 4,
                     &Kp[(size_t)plane * Mrows * PW +
                         (size_t)(b * Sq + tc * 128 + tokl) * PW + h * 32 + qw]);
            }
            cp_commit();
        };

        __syncthreads();   // protect sQ/sS reuse from previous mode
        {   // stage Q: 512 cp16 in one sweep
            int plane = tid >> 8, rem = tid & 255;
            int row = rem >> 3, qw = (rem & 7) * 4;
            cp16(sq_b + (uint32_t)(plane * 1152 + row * 36 + qw) * 4,
                 &Qp[(size_t)plane * Mrows * PW +
                     (size_t)(b * Sq + q0 + row) * PW + h * 32 + qw]);
        }
        stageK(tc_lo, 0);

        for (int tc = tc_lo; tc < tc_hi; tc++) {
            const int bufc = (tc - tc_lo) & 1;
            if (tc + 1 < tc_hi) { stageK(tc + 1, bufc ^ 1); cp_wait<1>(); }
            else                { cp_wait<0>(); }
            __syncthreads();

            const int cb = tc * 128;
            const bool warp_do =
                (mode == 0) ? (cb + ct * 16 <= q0 + 31) :
                (mode == 1) ? (cb + ct * 16 + 15 >= q0) : true;
            if (warp_do) {
                float accp[2][4];
#pragma unroll
                for (int nf = 0; nf < 2; nf++)
#pragma unroll
                    for (int i = 0; i < 4; i++) accp[nf][i] = 0.0f;
                const uint32_t kbb = skb_b + (uint32_t)(bufc * KBUF) * 4;
#pragma unroll
                for (int ks = 0; ks < 4; ks++) {
                    const int qw = ks * 8;
                    uint32_t ah[4], al[4], bfr[4], blr[4];
                    uint32_t aaddr = sq_b +
                        (uint32_t)((rt * 16 + a_r) * 36 + qw + a_w) * 4;
                    ldsm4(ah, aaddr);
                    ldsm4(al, aaddr + 1152 * 4);
                    uint32_t baddr = kbb +
                        (uint32_t)((ct * 16 + b_r) * 36 + qw + b_w) * 4;
                    ldsm4(bfr, baddr);
                    ldsm4(blr, baddr + 4608 * 4);
#pragma unroll
                    for (int nf = 0; nf < 2; nf++) {
                        mma16(accp[nf], ah, &bfr[nf * 2]);
                        mma16(accp[nf], ah, &blr[nf * 2]);
                        mma16(accp[nf], al, &bfr[nf * 2]);
                    }
                }
#pragma unroll
                for (int nf = 0; nf < 2; nf++) {
                    int col = cb + ct * 16 + nf * 8 + 2 * t;
                    *(float2*)&sS[(rt * 16 + g) * SS_STR + col] =
                        make_float2(accp[nf][0], accp[nf][1]);
                    *(float2*)&sS[(rt * 16 + 8 + g) * SS_STR + col] =
                        make_float2(accp[nf][2], accp[nf][3]);
                }
            }
            __syncthreads();
        }

        // ---------------- consumer: single pass, 8 q-groups x 4 rows ----------
        if (mode < 2) {
            const bool skipc = (mode == 0 && c_lo > qmin + 3) ||
                               (mode == 1 && c_hi < qmin);
            float acc[4][8];
            float tval[4];
#pragma unroll
            for (int r = 0; r < 4; r++) {
                if (skipc) {
#pragma unroll
                    for (int c = 0; c < 8; c++) acc[r][c] = 0.0f;
                    tval[r] = 0.0f;
                    if (lane == 31) sRed[(qg * 4 + r) * 2 + half] = 0.0f;
                } else {
                    const float* srow = &sS[(qg * 4 + r) * SS_STR + kg * 8];
                    float4 s0 = *(const float4*)&srow[0];
                    float4 s1 = *(const float4*)&srow[4];
                    acc[r][0] = s0.x; acc[r][1] = s0.y; acc[r][2] = s0.z; acc[r][3] = s0.w;
                    acc[r][4] = s1.x; acc[r][5] = s1.y; acc[r][6] = s1.z; acc[r][7] = s1.w;
                    int q = qmin + r;
                    if (mode == 0) {
#pragma unroll
                        for (int c = 0; c < 8; c++)
                            if (kg * 8 + c > q) acc[r][c] = -1.0e9f;
                    } else {
#pragma unroll
                        for (int c = 0; c < 8; c++)
                            if (kg * 8 + c < q) acc[r][c] = -1.0e9f;
                    }
                    float run = 0.0f;
#pragma unroll
                    for (int c = 0; c < 8; c++) {
                        run += __expf(acc[r][c]);
                        acc[r][c] = run;
                    }
                    float tv = run;
#pragma unroll
                    for (int off = 1; off < 32; off <<= 1) {
                        float u = __shfl_up_sync(0xffffffffu, tv, off);
                        if (lane >= off) tv += u;
                    }
                    tval[r] = tv;
                    if (lane == 31) sRed[(qg * 4 + r) * 2 + half] = tv;
                }
            }
            __syncthreads();
#pragma unroll
            for (int r = 0; r < 4; r++) {
                float w0 = sRed[(qg * 4 + r) * 2 + 0], w1 = sRed[(qg * 4 + r) * 2 + 1];
                float sumrow = w0 + w1;
                float tot = acc[r][7];
                float excl = (half ? w0 : 0.0f) + (tval[r] - tot);
                float inv = 1.0f / sumrow;
                float* mrow_p = &sMK[(qg * 4 + r) * 512 + kg * 8];
                if (mode == 0) {
                    float v[8];
#pragma unroll
                    for (int c = 0; c < 8; c++)
                        v[c] = (excl + acc[r][c]) * inv;
                    *(float4*)&mrow_p[0] = make_float4(v[0], v[1], v[2], v[3]);
                    *(float4*)&mrow_p[4] = make_float4(v[4], v[5], v[6], v[7]);
                } else {
                    float4 m0 = *(const float4*)&mrow_p[0];
                    float4 m1 = *(const float4*)&mrow_p[4];
                    float m[8] = {m0.x, m0.y, m0.z, m0.w, m1.x, m1.y, m1.z, m1.w};
                    float base = sumrow - excl;
                    m[0] *= base * inv;
#pragma unroll
                    for (int c = 1; c < 8; c++)
                        m[c] *= (base - acc[r][c - 1]) * inv;
                    *(float4*)&mrow_p[0] = make_float4(m[0], m[1], m[2], m[3]);
                    *(float4*)&mrow_p[4] = make_float4(m[4], m[5], m[6], m[7]);
                }
            }
            __syncthreads();
        } else {
            float lsum = 0.0f;
            float acc[4][8];
#pragma unroll
            for (int r = 0; r < 4; r++) {
                const float* srow = &sS[(qg * 4 + r) * SS_STR + kg * 8];
                float4 s0 = *(const float4*)&srow[0];
                float4 s1 = *(const float4*)&srow[4];
                acc[r][0] = s0.x; acc[r][1] = s0.y; acc[r][2] = s0.z; acc[r][3] = s0.w;
                acc[r][4] = s1.x; acc[r][5] = s1.y; acc[r][6] = s1.z; acc[r][7] = s1.w;
                const float* mrow_p = &sMK[(qg * 4 + r) * 512 + kg * 8];
                float4 m0 = *(const float4*)&mrow_p[0];
                float4 m1 = *(const float4*)&mrow_p[4];
                float m[8] = {m0.x, m0.y, m0.z, m0.w, m1.x, m1.y, m1.z, m1.w};
#pragma unroll
                for (int c = 0; c < 8; c++)
                    acc[r][c] = (acc[r][c] - rmq[r] - rmk[c]) * m[c];
            }
            float mrow[4];
#pragma unroll
            for (int r = 0; r < 4; r++) {
                float m = acc[r][0];
#pragma unroll
                for (int c = 1; c < 8; c++) m = fmaxf(m, acc[r][c]);
#pragma unroll
                for (int off = 16; off >= 1; off >>= 1)
                    m = fmaxf(m, __shfl_xor_sync(0xffffffffu, m, off));
                if (lane == 0) sRed[(qg * 4 + r) * 2 + half] = m;
            }
            __syncthreads();
#pragma unroll
            for (int r = 0; r < 4; r++)
                mrow[r] = fmaxf(sRed[(qg * 4 + r) * 2 + 0], sRed[(qg * 4 + r) * 2 + 1]);
            __syncthreads();

#pragma unroll
            for (int r = 0; r < 4; r++) {
                float s = 0.0f;
#pragma unroll
                for (int c = 0; c < 8; c++) {
                    acc[r][c] = __expf(acc[r][c] - mrow[r]);
                    s += acc[r][c];
                }
#pragma unroll
                for (int off = 16; off >= 1; off >>= 1)
                    s += __shfl_xor_sync(0xffffffffu, s, off);
                if (lane == 0) sRed[(qg * 4 + r) * 2 + half] = s;
            }
            __syncthreads();
#pragma unroll
            for (int r = 0; r < 4; r++) {
                int q = qmin + r;
                float inv = 1.0f / (sRed[(qg * 4 + r) * 2 + 0] + sRed[(qg * 4 + r) * 2 + 1]);
                size_t oidx = ((size_t)bh * Sq + q) * Sq + kg * 8;
                size_t sidx = ((size_t)((h * Bq + b) * Sq + q)) * Sq + kg * 8;
                float4 sp0 = *(const float4*)&span[sidx];
                float4 sp1 = *(const float4*)&span[sidx + 4];
                float sp[8] = {sp0.x, sp0.y, sp0.z, sp0.w, sp1.x, sp1.y, sp1.z, sp1.w};
                float pv[8];
#pragma unroll
                for (int c = 0; c < 8; c++) pv[c] = acc[r][c] * inv;
                float4 o0 = {pv[0], pv[1], pv[2], pv[3]};
                float4 o1 = {pv[4], pv[5], pv[6], pv[7]};
                *(float4*)&out[oidx]     = o0;
                *(float4*)&out[oidx + 4] = o1;
#pragma unroll
                for (int c = 0; c < 8; c++)
                    lsum += softplus_neg01(pv[c]) + pv[c] * (1.0f - sp[c]);
            }
#pragma unroll
            for (int off = 16; off >= 1; off >>= 1)
                lsum += __shfl_xor_sync(0xffffffffu, lsum, off);
            __syncthreads();
            if (lane == 0) sW[warp] = lsum;
            __syncthreads();
            if (tid == 0) {
                float tot = 0.0f;
#pragma unroll
                for (int ww = 0; ww < 16; ww++) tot += sW[ww];
                atomicAdd(&g_loss, (double)tot);
            }
        }
    }
}

__global__ void finalize_kernel(float* out, int out_size) {
    if (out_size > NATT)
        out[NATT] = (float)(g_loss / (double)NATT);
}

// ---------------------------------------------------------------------------
extern "C" void kernel_launch(void* const* d_in, const int* in_sizes, int n_in,
                              void* d_out, int out_size)
{
    (void)in_sizes; (void)n_in;
    const float* query = (const float*)d_in[0];
    const float* key   = (const float*)d_in[1];
    const float* mask  = (const float*)d_in[2];
    const float* span  = (const float*)d_in[3];
    float* out = (float*)d_out;

    Ptr6 ws, bs;
    for (int w = 0; w < 6; w++) {
        ws.p[w] = (const float*)d_in[4 + 2 * w];
        bs.p[w] = (const float*)d_in[5 + 2 * w];
    }

    cudaFuncSetAttribute(gemm_mma, cudaFuncAttributeMaxDynamicSharedMemorySize, DYN_SMEM);
    cudaFuncSetAttribute(attn_fused, cudaFuncAttributeMaxDynamicSharedMemorySize, ATTN_SMEM_BYTES);

    pack_qk<<<dim3(Mrows * PW / 256, 2), 256>>>(query, key);
    transpose_pack6<<<dim3(Dm / 32, Dm / 32, 6), dim3(32, 8)>>>(ws);
    gemm_mma<<<dim3(Mrows / BM, Dm / BN, 6), 256, DYN_SMEM>>>(bs);
    attn_fused<<<dim3(Sq / QROWS, BHn), 512, ATTN_SMEM_BYTES>>>(mask, span, out);
    finalize_kernel<<<1, 1>>>(out, out_size);
}